// round 1
// baseline (speedup 1.0000x reference)
#include <cuda_runtime.h>
#include <cuda_fp16.h>

#define BB 16
#define MM 2048
#define NN 2048
#define R  16            // rows per tile in the iteration kernel
#define ITER_THREADS 512
#define NITER 100
#define SMEM_ITER (R*NN*2 + 256*4 + 16*4)   // tile + red + zs = 66624 B

// Scratch (static __device__ globals -- no runtime allocation)
__device__ __half g_K[(size_t)BB * MM * NN];   // 134 MB fp16 kernel matrix
__device__ float  g_T[3][BB * NN];             // triple-buffered column sums
__device__ float  g_z[BB * MM];                // current z = exp(u)

struct alignas(8) Half4 { __half2 a, b; };

// ---------------------------------------------------------------------------
// K = exp(-C / eps) = exp(-10 C), stored fp16. One float4 per thread.
// ---------------------------------------------------------------------------
__global__ void build_K_kernel(const float* __restrict__ C) {
    size_t i = (size_t)blockIdx.x * blockDim.x + threadIdx.x;   // float4 index
    float4 c = ((const float4*)C)[i];
    __half2 h01 = __floats2half2_rn(__expf(-10.f * c.x), __expf(-10.f * c.y));
    __half2 h23 = __floats2half2_rn(__expf(-10.f * c.z), __expf(-10.f * c.w));
    Half4 o; o.a = h01; o.b = h23;
    ((Half4*)g_K)[i] = o;
}

// ---------------------------------------------------------------------------
// T[0] = b  (so the first iteration sees w = b/T = 1, matching v0 = 0),
// T[1] = T[2] = 0, distance accumulators = 0.
// ---------------------------------------------------------------------------
__global__ void init_kernel(const float* __restrict__ b, float* __restrict__ out) {
    int i = blockIdx.x * blockDim.x + threadIdx.x;   // < BB*NN = 32768
    float bv = b[i];
    g_T[0][i] = bv;
    g_T[1][i] = 0.f;
    g_T[2][i] = 0.f;
    if (i < BB) out[i] = 0.f;
}

// ---------------------------------------------------------------------------
// One Sinkhorn iteration (fused row pass + column pass, single K read):
//   w_j = b_j / T_in_j          (registers, per-thread 4 columns)
//   S_i = sum_j K_ij w_j        (phase 1: column-threaded partials + reduce)
//   z_i = a_i / S_i             (stored to g_z and smem)
//   T_out_j += sum_i K_ij z_i   (phase 2: smem tile re-read, global atomics)
// Also zeroes its slice of T[zeroIdx] (needed two iterations later).
// Grid: (MM/R, BB) = (128, 16); 512 threads; 66624 B dynamic smem.
// ---------------------------------------------------------------------------
__global__ void __launch_bounds__(ITER_THREADS, 3)
sinkhorn_iter(const float* __restrict__ a, const float* __restrict__ b,
              int inIdx, int outIdx, int zeroIdx) {
    extern __shared__ unsigned char smem[];
    __half2* tile = (__half2*)smem;                      // R x 1024 half2
    float*   red  = (float*)(smem + (size_t)R * NN * 2); // 16 rows x 16 warps
    float*   zs   = red + 256;                           // R values

    const int batch = blockIdx.y;
    const int rb    = blockIdx.x;
    const int tid   = threadIdx.x;
    const int warp  = tid >> 5, lane = tid & 31;
    const int row0  = rb * R;

    // Stage tile: R*NN fp16 = 64 KB, 8 x uint4 per thread
    {
        const uint4* src = (const uint4*)(g_K + ((size_t)batch * MM + row0) * NN);
        uint4* dst = (uint4*)smem;
        #pragma unroll
        for (int k = 0; k < 8; k++)
            dst[tid + k * ITER_THREADS] = src[tid + k * ITER_THREADS];
    }

    // w for this thread's 4 columns: (2t,2t+1) and (2t+1024,2t+1025)
    const float2* b2 = (const float2*)(b + batch * NN);
    const float2* t2 = (const float2*)(g_T[inIdx] + batch * NN);
    float2 bv0 = b2[tid], bv1 = b2[tid + 512];
    float2 tv0 = t2[tid], tv1 = t2[tid + 512];
    float2 w0 = make_float2(__fdividef(bv0.x, tv0.x), __fdividef(bv0.y, tv0.y));
    float2 w1 = make_float2(__fdividef(bv1.x, tv1.x), __fdividef(bv1.y, tv1.y));

    // Zero slice of the buffer used two iterations from now (2048/128 = 16 per CTA)
    if (tid < 16) g_T[zeroIdx][batch * NN + rb * 16 + tid] = 0.f;

    __syncthreads();

    // Phase 1: row sums. Each thread contributes its 4 columns, warp-reduce,
    // then 16-warp partials reduced by one warp per row.
    #pragma unroll
    for (int i = 0; i < R; i++) {
        float2 k0 = __half22float2(tile[i * (NN / 2) + tid]);
        float2 k1 = __half22float2(tile[i * (NN / 2) + tid + 512]);
        float v = k0.x * w0.x + k0.y * w0.y + k1.x * w1.x + k1.y * w1.y;
        v += __shfl_xor_sync(0xffffffffu, v, 16);
        v += __shfl_xor_sync(0xffffffffu, v, 8);
        v += __shfl_xor_sync(0xffffffffu, v, 4);
        v += __shfl_xor_sync(0xffffffffu, v, 2);
        v += __shfl_xor_sync(0xffffffffu, v, 1);
        if (lane == 0) red[i * 16 + warp] = v;
    }
    __syncthreads();

    {   // warp i reduces row i over the 16 warp-partials
        float v = (lane < 16) ? red[warp * 16 + lane] : 0.f;
        v += __shfl_xor_sync(0xffffffffu, v, 8);
        v += __shfl_xor_sync(0xffffffffu, v, 4);
        v += __shfl_xor_sync(0xffffffffu, v, 2);
        v += __shfl_xor_sync(0xffffffffu, v, 1);
        if (lane == 0) {
            float zi = __fdividef(__ldg(&a[batch * MM + row0 + warp]), v);
            zs[warp] = zi;
            g_z[batch * MM + row0 + warp] = zi;
        }
    }
    __syncthreads();

    // Phase 2: column partials from smem, atomic accumulate into T_out
    float2 acc0 = make_float2(0.f, 0.f), acc1 = make_float2(0.f, 0.f);
    #pragma unroll
    for (int i = 0; i < R; i++) {
        float zi = zs[i];
        float2 k0 = __half22float2(tile[i * (NN / 2) + tid]);
        float2 k1 = __half22float2(tile[i * (NN / 2) + tid + 512]);
        acc0.x += k0.x * zi; acc0.y += k0.y * zi;
        acc1.x += k1.x * zi; acc1.y += k1.y * zi;
    }
    float* To = g_T[outIdx] + batch * NN;
    atomicAdd(&To[2 * tid],        acc0.x);
    atomicAdd(&To[2 * tid + 1],    acc0.y);
    atomicAdd(&To[2 * tid + 1024], acc1.x);
    atomicAdd(&To[2 * tid + 1025], acc1.y);
}

// ---------------------------------------------------------------------------
// P_ij = z_i * exp(-10 C_ij) * w_j  (exact fp32 K for the output),
// distance_b = sum_ij P_ij C_ij.
// Grid: (MM/8, BB); 256 threads; each CTA does 8 rows x 2048 cols.
// ---------------------------------------------------------------------------
__global__ void __launch_bounds__(256)
finalize_kernel(const float* __restrict__ C, const float* __restrict__ b,
                float* __restrict__ out, int tIdx) {
    const int batch = blockIdx.y;
    const int rb    = blockIdx.x;
    const int tid   = threadIdx.x;

    const float4* b4 = (const float4*)(b + batch * NN);
    const float4* t4 = (const float4*)(g_T[tIdx] + batch * NN);
    float4 bv0 = b4[tid], bv1 = b4[tid + 256];
    float4 tv0 = t4[tid], tv1 = t4[tid + 256];
    float4 w0 = make_float4(bv0.x / tv0.x, bv0.y / tv0.y, bv0.z / tv0.z, bv0.w / tv0.w);
    float4 w1 = make_float4(bv1.x / tv1.x, bv1.y / tv1.y, bv1.z / tv1.z, bv1.w / tv1.w);

    const size_t rowbase = (size_t)batch * MM + rb * 8;
    float* P = out + BB;
    float acc = 0.f;

    #pragma unroll
    for (int i = 0; i < 8; i++) {
        float zi = g_z[rowbase + i];
        const float4* Crow = (const float4*)(C + (rowbase + i) * NN);
        float4 c0 = Crow[tid], c1 = Crow[tid + 256];
        float4 p0, p1;
        p0.x = zi * __expf(-10.f * c0.x) * w0.x;
        p0.y = zi * __expf(-10.f * c0.y) * w0.y;
        p0.z = zi * __expf(-10.f * c0.z) * w0.z;
        p0.w = zi * __expf(-10.f * c0.w) * w0.w;
        p1.x = zi * __expf(-10.f * c1.x) * w1.x;
        p1.y = zi * __expf(-10.f * c1.y) * w1.y;
        p1.z = zi * __expf(-10.f * c1.z) * w1.z;
        p1.w = zi * __expf(-10.f * c1.w) * w1.w;
        float4* Prow = (float4*)(P + (rowbase + i) * NN);
        Prow[tid]       = p0;
        Prow[tid + 256] = p1;
        acc += p0.x * c0.x + p0.y * c0.y + p0.z * c0.z + p0.w * c0.w
             + p1.x * c1.x + p1.y * c1.y + p1.z * c1.z + p1.w * c1.w;
    }

    // Block-reduce distance partial, one atomic per CTA per batch
    #pragma unroll
    for (int off = 16; off; off >>= 1)
        acc += __shfl_xor_sync(0xffffffffu, acc, off);
    __shared__ float rbuf[8];
    int warp = tid >> 5, lane = tid & 31;
    if (lane == 0) rbuf[warp] = acc;
    __syncthreads();
    if (tid == 0) {
        float s = 0.f;
        #pragma unroll
        for (int k = 0; k < 8; k++) s += rbuf[k];
        atomicAdd(&out[batch], s);
    }
}

// ---------------------------------------------------------------------------
extern "C" void kernel_launch(void* const* d_in, const int* in_sizes, int n_in,
                              void* d_out, int out_size) {
    const float* C = (const float*)d_in[0];   // (16, 2048, 2048)
    const float* a = (const float*)d_in[1];   // (16, 2048)
    const float* b = (const float*)d_in[2];   // (16, 2048)
    float* out = (float*)d_out;               // [0..16) distance, [16..) P

    cudaFuncSetAttribute(sinkhorn_iter,
                         cudaFuncAttributeMaxDynamicSharedMemorySize, SMEM_ITER);

    // 16*2048*2048 / 4 float4s / 256 threads = 65536 blocks (exact)
    build_K_kernel<<<65536, 256>>>(C);
    init_kernel<<<(BB * NN) / 256, 256>>>(b, out);

    for (int k = 0; k < NITER; k++) {
        sinkhorn_iter<<<dim3(MM / R, BB), ITER_THREADS, SMEM_ITER>>>(
            a, b, k % 3, (k + 1) % 3, (k + 2) % 3);
    }

    finalize_kernel<<<dim3(MM / 8, BB), 256>>>(C, b, out, NITER % 3);
}